// round 16
// baseline (speedup 1.0000x reference)
#include <cuda_runtime.h>
#include <cuda_bf16.h>
#include <cstdint>

// PrRoIPool2D, separable two-pass, warp-private pipeline (ONE block barrier).
// Fixed shapes: features [2, 256, 50, 50] f32, rois [256, 5], out [256,256,7,7] f32.
//
// Block = (roi, 32-channel group), 256 threads, 6 blocks/SM.
// ch = tid>>3  =>  warp w owns channels 4w..4w+3 through BOTH passes:
//   y-pass writes warp-private ytmp, __syncwarp, x-pass reads it and stores
//   its 196 contiguous output floats straight to gmem (coalesced).
//  1) Parallel setup (the ONLY __syncthreads): 128 thr -> dense wyfull[h][p]
//     (1/area folded); 28 thr -> 4-tap x table (offsets vs even wstart2).
//  2) y-pass (adaptive): ww2<=8 scalar / ww2>8 float2 loads, cells read once.
//  3) x-pass in-warp: 7 iterations over the warp's 196 outputs, direct STG.

#define PH 7
#define PW 7
#define KW 4
#define CG 32
#define SCALE 0.0625f
#define YPITCH 17                    // per-(ch,p) row pitch in ytmp
#define WREG (4 * PH * YPITCH)       // 476 floats of ytmp per warp

#define C_   256
#define H_   50
#define W_   50
#define HW_  (H_ * W_)
#define CHW_ (C_ * HW_)

__device__ __forceinline__ float hat_cdf(float t) {
    t = fminf(fmaxf(t, -1.0f), 1.0f);
    return (t < 0.0f) ? 0.5f * (t + 1.0f) * (t + 1.0f)
                      : 0.5f + t - 0.5f * t * t;
}

__global__ void __launch_bounds__(256, 6)
prroi_pool_kernel(const float* __restrict__ feat,
                  const float* __restrict__ rois,
                  float* __restrict__ out)
{
    const int r  = blockIdx.x >> 3;
    const int cg = blockIdx.x & 7;

    __shared__ __align__(16) float s_ytmp[8 * WREG];    // 14.9 KB, warp-private slabs
    __shared__ __align__(16) float s_wyfull[16][8];     // [h][p], 1/area folded
    __shared__ __align__(16) float s_wx[PW][KW];
    __shared__ int s_offx[PW];

    const int tid  = threadIdx.x;
    const int lane = tid & 31;
    const int warp = tid >> 5;

    // ---- 0: window bounds (uniform per thread, broadcast roi loads) ----
    const float* roi = rois + r * 5;
    const float b0 = roi[0];
    const float x1 = roi[1] * SCALE;
    const float y1 = roi[2] * SCALE;
    const float x2 = roi[3] * SCALE;
    const float y2 = roi[4] * SCALE;
    const float bw = (x2 - x1) * (1.0f / PW);
    const float bh = (y2 - y1) * (1.0f / PH);

    const int hstart  = min(max((int)ceilf(y1 - 1.0f), 0), H_ - KW);
    const int wstart  = min(max((int)ceilf(x1 - 1.0f), 0), W_ - KW);
    const int hend    = min(max((int)ceilf(y1 + 6.0f * bh - 1.0f), 0), H_ - KW);
    const int wend    = min(max((int)ceilf(x1 + 6.0f * bw - 1.0f), 0), W_ - KW);
    const int wstart2 = wstart & ~1;               // even -> 8B-aligned float2 loads
    const int wh  = hend + KW - hstart;            // <= 15 (block-uniform)
    const int ww2 = wend + KW - wstart2;           // <= 16
    const int base = (int)b0 * CHW_ + cg * (CG * HW_);

    const float area = bw * bh;
    const float inva = (area > 0.0f) ? (1.0f / area) : 0.0f;

    // ---- 1: parallel weight setup, the only block barrier ----
    if (tid < 128) {                               // dense wyfull[h][p]
        const int h = tid >> 3;
        const int p = tid & 7;
        const float lo = y1 + (float)p * bh;
        const float hi = lo + bh;
        const float hf = (float)(hstart + h);
        float w = (hat_cdf(hi - hf) - hat_cdf(lo - hf)) * inva;
        if (p >= PH || (hstart + h) >= H_) w = 0.0f;
        s_wyfull[h][p] = w;
    } else if (tid < 128 + PW * KW) {              // x table + offsets (vs wstart2)
        const int z = tid - 128;
        const int q = z >> 2;
        const int k = z & 3;
        const float lo = x1 + (float)q * bw;
        const float hi = lo + bw;
        const int i0 = min(max((int)ceilf(lo - 1.0f), 0), W_ - KW);
        s_wx[q][k] = hat_cdf(hi - (float)(i0 + k)) - hat_cdf(lo - (float)(i0 + k));
        if (k == 0) s_offx[q] = i0 - wstart2;
    }
    __syncthreads();

    float* ywarp = s_ytmp + warp * WREG;           // this warp's private slab
    const int ch  = tid >> 3;                      // 0..31 (4 per warp)
    const int chl = ch & 3;                        // channel within warp

    // ---- 2: y-pass (block-uniform adaptive); warp-private stores ----
    if (ww2 <= 8) {
        const int x = tid & 7;                     // 0..7
        if (x < ww2) {
            const float* gp = feat + base + ch * HW_ + hstart * W_ + wstart2 + x;
            float acc[PH];
            #pragma unroll
            for (int p = 0; p < PH; p++) acc[p] = 0.0f;

            #pragma unroll
            for (int c = 0; c < 15; c += 5) {
                if (c < wh) {
                    float v[5];
                    #pragma unroll
                    for (int j = 0; j < 5; j++) {
                        const int h = c + j;
                        v[j] = (h < wh) ? gp[h * W_] : 0.0f;
                    }
                    #pragma unroll
                    for (int j = 0; j < 5; j++) {
                        const int h = c + j;
                        const float4 wa = *reinterpret_cast<const float4*>(&s_wyfull[h][0]);
                        const float4 wb = *reinterpret_cast<const float4*>(&s_wyfull[h][4]);
                        acc[0] = fmaf(v[j], wa.x, acc[0]);
                        acc[1] = fmaf(v[j], wa.y, acc[1]);
                        acc[2] = fmaf(v[j], wa.z, acc[2]);
                        acc[3] = fmaf(v[j], wa.w, acc[3]);
                        acc[4] = fmaf(v[j], wb.x, acc[4]);
                        acc[5] = fmaf(v[j], wb.y, acc[5]);
                        acc[6] = fmaf(v[j], wb.z, acc[6]);
                    }
                }
            }
            #pragma unroll
            for (int p = 0; p < PH; p++)
                ywarp[(chl * PH + p) * YPITCH + x] = acc[p];
        }
    } else {
        const int xp = tid & 7;
        const int x0 = 2 * xp;
        if (x0 < ww2) {
            const float* gp = feat + base + ch * HW_ + hstart * W_ + wstart2 + x0;
            float2 acc[PH];
            #pragma unroll
            for (int p = 0; p < PH; p++) acc[p] = make_float2(0.0f, 0.0f);

            #pragma unroll
            for (int c = 0; c < 15; c += 5) {
                if (c < wh) {
                    float2 v[5];
                    #pragma unroll
                    for (int j = 0; j < 5; j++) {
                        const int h = c + j;
                        v[j] = (h < wh) ? *reinterpret_cast<const float2*>(gp + h * W_)
                                        : make_float2(0.0f, 0.0f);
                    }
                    #pragma unroll
                    for (int j = 0; j < 5; j++) {
                        const int h = c + j;
                        const float4 wa = *reinterpret_cast<const float4*>(&s_wyfull[h][0]);
                        const float4 wb = *reinterpret_cast<const float4*>(&s_wyfull[h][4]);
                        acc[0].x = fmaf(v[j].x, wa.x, acc[0].x); acc[0].y = fmaf(v[j].y, wa.x, acc[0].y);
                        acc[1].x = fmaf(v[j].x, wa.y, acc[1].x); acc[1].y = fmaf(v[j].y, wa.y, acc[1].y);
                        acc[2].x = fmaf(v[j].x, wa.z, acc[2].x); acc[2].y = fmaf(v[j].y, wa.z, acc[2].y);
                        acc[3].x = fmaf(v[j].x, wa.w, acc[3].x); acc[3].y = fmaf(v[j].y, wa.w, acc[3].y);
                        acc[4].x = fmaf(v[j].x, wb.x, acc[4].x); acc[4].y = fmaf(v[j].y, wb.x, acc[4].y);
                        acc[5].x = fmaf(v[j].x, wb.y, acc[5].x); acc[5].y = fmaf(v[j].y, wb.y, acc[5].y);
                        acc[6].x = fmaf(v[j].x, wb.z, acc[6].x); acc[6].y = fmaf(v[j].y, wb.z, acc[6].y);
                    }
                }
            }
            #pragma unroll
            for (int p = 0; p < PH; p++) {
                const int bi = (chl * PH + p) * YPITCH + x0;
                ywarp[bi]     = acc[p].x;
                ywarp[bi + 1] = acc[p].y;
            }
        }
    }
    __syncwarp(0xffffffff);                        // producer == consumer warp

    // ---- 3: in-warp x-pass + direct coalesced gmem store ----
    {
        // warp's 196 outputs are contiguous: channels 4*warp .. 4*warp+3
        float* o = out + r * (C_ * PH * PW) + (cg * CG + 4 * warp) * (PH * PW);
        #pragma unroll
        for (int k = 0; k < 7; k++) {
            const int idx = lane + k * 32;         // 0..195 (+pad)
            if (idx < 4 * PH * PW) {
                const int cl  = idx / (PH * PW);   // const divisors -> mulhi
                const int rem = idx - cl * (PH * PW);
                const int p   = rem / PW;
                const int q   = rem - p * PW;

                const int xo = s_offx[q];
                const float4 wx = *reinterpret_cast<const float4*>(s_wx[q]);
                const float* yt = ywarp + (cl * PH + p) * YPITCH + xo;
                float v = yt[0] * wx.x;
                v = fmaf(yt[1], wx.y, v);
                v = fmaf(yt[2], wx.z, v);
                v = fmaf(yt[3], wx.w, v);
                o[idx] = v;                        // lane-consecutive -> coalesced
            }
        }
    }
}

extern "C" void kernel_launch(void* const* d_in, const int* in_sizes, int n_in,
                              void* d_out, int out_size)
{
    const float* feat = (const float*)d_in[0];
    const float* rois = (const float*)d_in[1];
    float* out = (float*)d_out;

    const int R = in_sizes[1] / 5;       // 256
    prroi_pool_kernel<<<R * (C_ / CG), 256>>>(feat, rois, out);
}

// round 17
// speedup vs baseline: 1.1128x; 1.1128x over previous
#include <cuda_runtime.h>
#include <cuda_bf16.h>
#include <cstdint>

// PrRoIPool2D, separable two-pass, exact-trip dynamic y-row loop.
// Fixed shapes: features [2, 256, 50, 50] f32, rois [256, 5], out [256,256,7,7] f32.
//
// Block = (roi, 32-channel group), 256 threads, 6 blocks/SM.
//  1) Parallel setup (ONE barrier): 128 thr -> dense wyfull[h][p] (1/area in),
//     28 thr -> 4-tap x table (offsets vs even wstart2 for aligned float2).
//  2) y-pass: dynamic h-loop of EXACTLY wh iterations (no predicates, no
//     zero-row work); adaptive scalar (small roi) / float2 (large roi) loads;
//     each feature cell read once -> ytmp[p][ch][x] (pitch 17).
//  3) x-pass: warp=p, lane=ch -> s_out (stride 49, conflict-free).
//  4) float4 coalesced writeback.

#define PH 7
#define PW 7
#define KW 4
#define CG 32
#define SCALE 0.0625f
#define YPITCH 17       // 17*ch mod 32 bijective -> conflict-free x-pass

#define C_   256
#define H_   50
#define W_   50
#define HW_  (H_ * W_)
#define CHW_ (C_ * HW_)

__device__ __forceinline__ float hat_cdf(float t) {
    t = fminf(fmaxf(t, -1.0f), 1.0f);
    return (t < 0.0f) ? 0.5f * (t + 1.0f) * (t + 1.0f)
                      : 0.5f + t - 0.5f * t * t;
}

__global__ void __launch_bounds__(256, 6)
prroi_pool_kernel(const float* __restrict__ feat,
                  const float* __restrict__ rois,
                  float* __restrict__ out)
{
    const int r  = blockIdx.x >> 3;
    const int cg = blockIdx.x & 7;

    __shared__ __align__(16) float s_ytmp[PH * CG * YPITCH];   // 15.2 KB
    __shared__ __align__(16) float s_out[CG * PH * PW];        // 6.3 KB
    __shared__ __align__(16) float s_wyfull[16][8];            // [h][p], 1/area folded
    __shared__ __align__(16) float s_wx[PW][KW];
    __shared__ int s_offx[PW];

    const int tid  = threadIdx.x;
    const int lane = tid & 31;

    // ---- 0: window bounds (uniform per thread, broadcast roi loads) ----
    const float* roi = rois + r * 5;
    const float b0 = roi[0];
    const float x1 = roi[1] * SCALE;
    const float y1 = roi[2] * SCALE;
    const float x2 = roi[3] * SCALE;
    const float y2 = roi[4] * SCALE;
    const float bw = (x2 - x1) * (1.0f / PW);
    const float bh = (y2 - y1) * (1.0f / PH);

    const int hstart  = min(max((int)ceilf(y1 - 1.0f), 0), H_ - KW);
    const int wstart  = min(max((int)ceilf(x1 - 1.0f), 0), W_ - KW);
    const int hend    = min(max((int)ceilf(y1 + 6.0f * bh - 1.0f), 0), H_ - KW);
    const int wend    = min(max((int)ceilf(x1 + 6.0f * bw - 1.0f), 0), W_ - KW);
    const int wstart2 = wstart & ~1;               // even -> 8B-aligned float2 loads
    const int wh  = hend + KW - hstart;            // <= 15 (block-uniform)
    const int ww2 = wend + KW - wstart2;           // <= 16
    const int base = (int)b0 * CHW_ + cg * (CG * HW_);

    const float area = bw * bh;
    const float inva = (area > 0.0f) ? (1.0f / area) : 0.0f;

    // ---- 1: parallel weight setup, one barrier ----
    if (tid < 128) {                               // dense wyfull[h][p]
        const int h = tid >> 3;
        const int p = tid & 7;
        const float lo = y1 + (float)p * bh;
        const float hi = lo + bh;
        const float hf = (float)(hstart + h);
        float w = (hat_cdf(hi - hf) - hat_cdf(lo - hf)) * inva;
        if (p >= PH || (hstart + h) >= H_) w = 0.0f;
        s_wyfull[h][p] = w;
    } else if (tid < 128 + PW * KW) {              // x table + offsets (vs wstart2)
        const int z = tid - 128;
        const int q = z >> 2;
        const int k = z & 3;
        const float lo = x1 + (float)q * bw;
        const float hi = lo + bw;
        const int i0 = min(max((int)ceilf(lo - 1.0f), 0), W_ - KW);
        s_wx[q][k] = hat_cdf(hi - (float)(i0 + k)) - hat_cdf(lo - (float)(i0 + k));
        if (k == 0) s_offx[q] = i0 - wstart2;
    }
    __syncthreads();

    // ---- 2: y-pass, exact-trip dynamic row loop (block-uniform adaptive) ----
    if (ww2 <= 8) {
        // small roi: thread = (x, ch), scalar loads
        const int x  = tid & 7;                    // 0..7
        const int ch = tid >> 3;                   // 0..31
        if (x < ww2) {
            const float* gp = feat + base + ch * HW_ + hstart * W_ + wstart2 + x;
            float acc[PH];
            #pragma unroll
            for (int p = 0; p < PH; p++) acc[p] = 0.0f;

            #pragma unroll 3
            for (int h = 0; h < wh; h++) {         // exactly wh rows, no predicates
                const float v = gp[h * W_];
                const float4 wa = *reinterpret_cast<const float4*>(&s_wyfull[h][0]);
                const float4 wb = *reinterpret_cast<const float4*>(&s_wyfull[h][4]);
                acc[0] = fmaf(v, wa.x, acc[0]);
                acc[1] = fmaf(v, wa.y, acc[1]);
                acc[2] = fmaf(v, wa.z, acc[2]);
                acc[3] = fmaf(v, wa.w, acc[3]);
                acc[4] = fmaf(v, wb.x, acc[4]);
                acc[5] = fmaf(v, wb.y, acc[5]);
                acc[6] = fmaf(v, wb.z, acc[6]);
            }
            #pragma unroll
            for (int p = 0; p < PH; p++)
                s_ytmp[(p * CG + ch) * YPITCH + x] = acc[p];
        }
    } else {
        // large roi: thread = (x-pair, ch), float2 loads
        const int xp = tid & 7;
        const int ch = tid >> 3;
        const int x0 = 2 * xp;
        if (x0 < ww2) {
            const float* gp = feat + base + ch * HW_ + hstart * W_ + wstart2 + x0;
            float2 acc[PH];
            #pragma unroll
            for (int p = 0; p < PH; p++) acc[p] = make_float2(0.0f, 0.0f);

            #pragma unroll 3
            for (int h = 0; h < wh; h++) {         // exactly wh rows, no predicates
                const float2 v = *reinterpret_cast<const float2*>(gp + h * W_);
                const float4 wa = *reinterpret_cast<const float4*>(&s_wyfull[h][0]);
                const float4 wb = *reinterpret_cast<const float4*>(&s_wyfull[h][4]);
                acc[0].x = fmaf(v.x, wa.x, acc[0].x); acc[0].y = fmaf(v.y, wa.x, acc[0].y);
                acc[1].x = fmaf(v.x, wa.y, acc[1].x); acc[1].y = fmaf(v.y, wa.y, acc[1].y);
                acc[2].x = fmaf(v.x, wa.z, acc[2].x); acc[2].y = fmaf(v.y, wa.z, acc[2].y);
                acc[3].x = fmaf(v.x, wa.w, acc[3].x); acc[3].y = fmaf(v.y, wa.w, acc[3].y);
                acc[4].x = fmaf(v.x, wb.x, acc[4].x); acc[4].y = fmaf(v.y, wb.x, acc[4].y);
                acc[5].x = fmaf(v.x, wb.y, acc[5].x); acc[5].y = fmaf(v.y, wb.y, acc[5].y);
                acc[6].x = fmaf(v.x, wb.z, acc[6].x); acc[6].y = fmaf(v.y, wb.z, acc[6].y);
            }
            #pragma unroll
            for (int p = 0; p < PH; p++) {
                const int bi = (p * CG + ch) * YPITCH + x0;
                s_ytmp[bi]     = acc[p].x;
                s_ytmp[bi + 1] = acc[p].y;
            }
        }
    }
    __syncthreads();

    // ---- 3: x-pass: warp = p, lane = ch ----
    {
        const int wp = tid >> 5;
        if (wp < PH) {
            const float* yt = s_ytmp + (wp * CG + lane) * YPITCH;
            float* so = s_out + lane * (PH * PW) + wp * PW;
            #pragma unroll
            for (int q = 0; q < PW; q++) {
                const int xo = s_offx[q];
                const float4 wx = *reinterpret_cast<const float4*>(s_wx[q]);
                float v = yt[xo] * wx.x;
                v = fmaf(yt[xo + 1], wx.y, v);
                v = fmaf(yt[xo + 2], wx.z, v);
                v = fmaf(yt[xo + 3], wx.w, v);
                so[q] = v;                         // ch stride 49 (odd): conflict-free
            }
        }
    }
    __syncthreads();

    // ---- 4: float4 coalesced writeback ----
    {
        float4* o4 = reinterpret_cast<float4*>(out + r * (C_ * PH * PW) + cg * (CG * PH * PW));
        const float4* s4 = reinterpret_cast<const float4*>(s_out);
        #pragma unroll
        for (int i = tid; i < (CG * PH * PW) / 4; i += 256)   // 392 float4s
            o4[i] = s4[i];
    }
}

extern "C" void kernel_launch(void* const* d_in, const int* in_sizes, int n_in,
                              void* d_out, int out_size)
{
    const float* feat = (const float*)d_in[0];
    const float* rois = (const float*)d_in[1];
    float* out = (float*)d_out;

    const int R = in_sizes[1] / 5;       // 256
    prroi_pool_kernel<<<R * (C_ / CG), 256>>>(feat, rois, out);
}